// round 2
// baseline (speedup 1.0000x reference)
#include <cuda_runtime.h>

#define B_  256
#define C_  3
#define H_  224
#define W_  224
#define HW_ (H_ * W_)          // 50176
#define HW4 (HW_ / 4)          // 12544 float4 per plane

// Scratch: per-(b,c) plane sums (no cudaMalloc allowed)
__device__ float g_sums[B_ * C_];

// ---------------------------------------------------------------------------
// Pass 1: per-plane sum. One block per (b,c) plane. Flip does not change the
// sum, gray/brightness are applied analytically in pass 2, so we reduce the
// ORIGINAL x.
// ---------------------------------------------------------------------------
__global__ __launch_bounds__(256) void plane_sum_kernel(const float* __restrict__ x) {
    const int plane = blockIdx.x;                       // b*3 + c
    const float4* __restrict__ px =
        reinterpret_cast<const float4*>(x + (size_t)plane * HW_);
    const int tid = threadIdx.x;

    float s = 0.0f;
    #pragma unroll 7
    for (int i = tid; i < HW4; i += 256) {              // 49 iterations
        float4 v = px[i];
        s += (v.x + v.y) + (v.z + v.w);
    }
    // warp reduce
    #pragma unroll
    for (int o = 16; o > 0; o >>= 1)
        s += __shfl_xor_sync(0xffffffffu, s, o);

    __shared__ float ws[8];
    if ((tid & 31) == 0) ws[tid >> 5] = s;
    __syncthreads();
    if (tid < 8) {
        s = ws[tid];
        #pragma unroll
        for (int o = 4; o > 0; o >>= 1)
            s += __shfl_xor_sync(0xffu, s, o);
        if (tid == 0) g_sums[plane] = s;
    }
}

// ---------------------------------------------------------------------------
// Pass 2: fused flip + gray + brightness + contrast + clip.
// blockIdx.y = batch index (per-batch params uniform across the block),
// blockIdx.x * 256 + tid = float4 pixel index within the plane.
// Each thread reads one float4 from each of the 3 channels (so gray costs no
// extra traffic) and writes 3 float4 outputs.
// Masks are int32 (harness promotes JAX bool -> int32).
// ---------------------------------------------------------------------------
__global__ __launch_bounds__(256) void transform_kernel(
    const float* __restrict__ x,
    const float* __restrict__ brightness,
    const float* __restrict__ contrast_factor,
    const int*   __restrict__ flip_mask,
    const int*   __restrict__ gray_mask,
    const int*   __restrict__ contrast_apply,
    float*       __restrict__ out)
{
    const int b = blockIdx.y;
    const int p = blockIdx.x * 256 + threadIdx.x;       // float4 idx in plane
    if (p >= HW4) return;

    // Per-batch scalars (broadcast loads, L1-resident)
    const float br   = brightness[b];
    const bool  flip = flip_mask[b] != 0;
    const bool  gray = gray_mask[b] != 0;
    const float cf   = contrast_apply[b] ? contrast_factor[b] : 1.0f;

    const float inv_hw = 1.0f / (float)HW_;
    const float m0 = g_sums[b * 3 + 0] * inv_hw;
    const float m1 = g_sums[b * 3 + 1] * inv_hw;
    const float m2 = g_sums[b * 3 + 2] * inv_hw;
    const float gw0 = 0.2989f, gw1 = 0.587f, gw2 = 0.114f;
    const float gm = gw0 * m0 + gw1 * m1 + gw2 * m2;

    // post-gray, post-brightness channel means
    const float mm0 = (gray ? gm : m0) * br;
    const float mm1 = (gray ? gm : m1) * br;
    const float mm2 = (gray ? gm : m2) * br;

    const float scale = br * cf;
    const float omcf  = 1.0f - cf;
    const float off0 = mm0 * omcf;
    const float off1 = mm1 * omcf;
    const float off2 = mm2 * omcf;

    // Source location (horizontal flip = mirrored float4, lanes reversed)
    const int pix  = p * 4;
    const int h    = pix / W_;
    const int w    = pix - h * W_;
    const int spix = flip ? (h * W_ + (W_ - 4 - w)) : pix;
    const int sp4  = spix >> 2;

    const float4* __restrict__ in4 =
        reinterpret_cast<const float4*>(x + (size_t)b * C_ * HW_);
    float4 v0 = in4[0 * HW4 + sp4];
    float4 v1 = in4[1 * HW4 + sp4];
    float4 v2 = in4[2 * HW4 + sp4];

    if (flip) {
        float t;
        t = v0.x; v0.x = v0.w; v0.w = t;  t = v0.y; v0.y = v0.z; v0.z = t;
        t = v1.x; v1.x = v1.w; v1.w = t;  t = v1.y; v1.y = v1.z; v1.z = t;
        t = v2.x; v2.x = v2.w; v2.w = t;  t = v2.y; v2.y = v2.z; v2.z = t;
    }

    if (gray) {
        float4 g;
        g.x = gw0 * v0.x + gw1 * v1.x + gw2 * v2.x;
        g.y = gw0 * v0.y + gw1 * v1.y + gw2 * v2.y;
        g.z = gw0 * v0.z + gw1 * v1.z + gw2 * v2.z;
        g.w = gw0 * v0.w + gw1 * v1.w + gw2 * v2.w;
        v0 = g; v1 = g; v2 = g;
    }

    #define XFORM(v, off)                                                    \
        v.x = fminf(fmaxf(fmaf(v.x, scale, off), -2.5f), 2.5f);             \
        v.y = fminf(fmaxf(fmaf(v.y, scale, off), -2.5f), 2.5f);             \
        v.z = fminf(fmaxf(fmaf(v.z, scale, off), -2.5f), 2.5f);             \
        v.w = fminf(fmaxf(fmaf(v.w, scale, off), -2.5f), 2.5f);
    XFORM(v0, off0)
    XFORM(v1, off1)
    XFORM(v2, off2)
    #undef XFORM

    float4* __restrict__ out4 =
        reinterpret_cast<float4*>(out + (size_t)b * C_ * HW_);
    out4[0 * HW4 + p] = v0;
    out4[1 * HW4 + p] = v1;
    out4[2 * HW4 + p] = v2;
}

extern "C" void kernel_launch(void* const* d_in, const int* in_sizes, int n_in,
                              void* d_out, int out_size) {
    const float* x   = (const float*)d_in[0];
    const float* br  = (const float*)d_in[1];
    const float* cfv = (const float*)d_in[2];
    const int*   fm  = (const int*)d_in[3];
    const int*   gm  = (const int*)d_in[4];
    const int*   ca  = (const int*)d_in[5];
    float* out = (float*)d_out;

    plane_sum_kernel<<<B_ * C_, 256>>>(x);
    dim3 grid((HW4 + 255) / 256, B_);                   // (49, 256)
    transform_kernel<<<grid, 256>>>(x, br, cfv, fm, gm, ca, out);
}

// round 3
// speedup vs baseline: 1.0039x; 1.0039x over previous
#include <cuda_runtime.h>

#define B_  256
#define C_  3
#define H_  224
#define W_  224
#define HW_ (H_ * W_)              // 50176
#define HW4 (HW_ / 4)              // 12544 float4 per plane
#define NT  1024
#define NITER ((HW4 + NT - 1) / NT) // 13

// One CTA per batch image. Phase 1: read image once (stage ch0 in smem) and
// compute per-channel sums. Phase 2: re-read ch1/ch2 (L2-hot, evict-first) +
// ch0 from smem, apply flip/gray/brightness/contrast/clip, stream out.
__global__ __launch_bounds__(NT) void fused_aug_kernel(
    const float* __restrict__ x,
    const float* __restrict__ brightness,
    const float* __restrict__ contrast_factor,
    const int*   __restrict__ flip_mask,
    const int*   __restrict__ gray_mask,
    const int*   __restrict__ contrast_apply,
    float*       __restrict__ out)
{
    extern __shared__ float4 s0[];          // channel-0 plane: 12544 float4 = 196KB
    __shared__ float red0[32], red1[32], red2[32];
    __shared__ float sm_sums[3];

    const int b   = blockIdx.x;
    const int tid = threadIdx.x;

    const float4* __restrict__ in4 =
        reinterpret_cast<const float4*>(x + (size_t)b * C_ * HW_);

    // ---------------- Phase 1: sum + stage ch0 ----------------
    float s_0 = 0.f, s_1 = 0.f, s_2 = 0.f;
    for (int i = tid; i < HW4; i += NT) {
        float4 a  = in4[i];
        s0[i] = a;
        s_0 += (a.x + a.y) + (a.z + a.w);
        float4 c1 = in4[HW4 + i];
        s_1 += (c1.x + c1.y) + (c1.z + c1.w);
        float4 c2 = in4[2 * HW4 + i];
        s_2 += (c2.x + c2.y) + (c2.z + c2.w);
    }
    #pragma unroll
    for (int o = 16; o; o >>= 1) {
        s_0 += __shfl_xor_sync(~0u, s_0, o);
        s_1 += __shfl_xor_sync(~0u, s_1, o);
        s_2 += __shfl_xor_sync(~0u, s_2, o);
    }
    if ((tid & 31) == 0) { red0[tid >> 5] = s_0; red1[tid >> 5] = s_1; red2[tid >> 5] = s_2; }
    __syncthreads();
    if (tid < 32) {
        float a0 = red0[tid], a1 = red1[tid], a2 = red2[tid];
        #pragma unroll
        for (int o = 16; o; o >>= 1) {
            a0 += __shfl_xor_sync(~0u, a0, o);
            a1 += __shfl_xor_sync(~0u, a1, o);
            a2 += __shfl_xor_sync(~0u, a2, o);
        }
        if (tid == 0) { sm_sums[0] = a0; sm_sums[1] = a1; sm_sums[2] = a2; }
    }
    __syncthreads();

    // ---------------- Per-batch coefficients ----------------
    const float br   = brightness[b];
    const bool  flip = flip_mask[b] != 0;
    const bool  gray = gray_mask[b] != 0;
    const float cf   = contrast_apply[b] ? contrast_factor[b] : 1.0f;

    const float inv_hw = 1.0f / (float)HW_;
    const float m0 = sm_sums[0] * inv_hw;
    const float m1 = sm_sums[1] * inv_hw;
    const float m2 = sm_sums[2] * inv_hw;
    const float gw0 = 0.2989f, gw1 = 0.587f, gw2 = 0.114f;
    const float gm  = gw0 * m0 + gw1 * m1 + gw2 * m2;

    const float mm0 = (gray ? gm : m0) * br;
    const float mm1 = (gray ? gm : m1) * br;
    const float mm2 = (gray ? gm : m2) * br;

    const float scale = br * cf;
    const float omcf  = 1.0f - cf;
    const float off0 = mm0 * omcf;
    const float off1 = mm1 * omcf;
    const float off2 = mm2 * omcf;

    float4* __restrict__ out4 =
        reinterpret_cast<float4*>(out + (size_t)b * C_ * HW_);

    // ---------------- Phase 2: transform (reverse order for L2 LIFO reuse) --
    for (int j = NITER - 1; j >= 0; --j) {
        const int p = j * NT + tid;
        if (p >= HW4) continue;

        const int pix  = p * 4;
        const int h    = pix / W_;
        const int w    = pix - h * W_;
        const int sp4  = flip ? ((h * W_ + (W_ - 4 - w)) >> 2) : p;

        float4 v0 = s0[sp4];
        float4 v1 = __ldcs(&in4[HW4 + sp4]);
        float4 v2 = __ldcs(&in4[2 * HW4 + sp4]);

        if (flip) {
            float t;
            t = v0.x; v0.x = v0.w; v0.w = t;  t = v0.y; v0.y = v0.z; v0.z = t;
            t = v1.x; v1.x = v1.w; v1.w = t;  t = v1.y; v1.y = v1.z; v1.z = t;
            t = v2.x; v2.x = v2.w; v2.w = t;  t = v2.y; v2.y = v2.z; v2.z = t;
        }

        if (gray) {
            float4 g;
            g.x = gw0 * v0.x + gw1 * v1.x + gw2 * v2.x;
            g.y = gw0 * v0.y + gw1 * v1.y + gw2 * v2.y;
            g.z = gw0 * v0.z + gw1 * v1.z + gw2 * v2.z;
            g.w = gw0 * v0.w + gw1 * v1.w + gw2 * v2.w;
            v0 = g; v1 = g; v2 = g;
        }

        #define XFORM(v, off)                                                \
            v.x = fminf(fmaxf(fmaf(v.x, scale, off), -2.5f), 2.5f);          \
            v.y = fminf(fmaxf(fmaf(v.y, scale, off), -2.5f), 2.5f);          \
            v.z = fminf(fmaxf(fmaf(v.z, scale, off), -2.5f), 2.5f);          \
            v.w = fminf(fmaxf(fmaf(v.w, scale, off), -2.5f), 2.5f);
        XFORM(v0, off0)
        XFORM(v1, off1)
        XFORM(v2, off2)
        #undef XFORM

        __stcs(&out4[0 * HW4 + p], v0);
        __stcs(&out4[1 * HW4 + p], v1);
        __stcs(&out4[2 * HW4 + p], v2);
    }
}

extern "C" void kernel_launch(void* const* d_in, const int* in_sizes, int n_in,
                              void* d_out, int out_size) {
    const float* x   = (const float*)d_in[0];
    const float* br  = (const float*)d_in[1];
    const float* cfv = (const float*)d_in[2];
    const int*   fm  = (const int*)d_in[3];
    const int*   gm  = (const int*)d_in[4];
    const int*   ca  = (const int*)d_in[5];
    float* out = (float*)d_out;

    const int smem_bytes = HW4 * (int)sizeof(float4);   // 200704
    cudaFuncSetAttribute(fused_aug_kernel,
                         cudaFuncAttributeMaxDynamicSharedMemorySize, smem_bytes);
    fused_aug_kernel<<<B_, NT, smem_bytes>>>(x, br, cfv, fm, gm, ca, out);
}